// round 5
// baseline (speedup 1.0000x reference)
#include <cuda_runtime.h>
#include <cuda_bf16.h>
#include <cstdint>

#define BATCH  4
#define SEQ    4096
#define HID    4096
#define OUTF   4096
#define RANK   64
#define NADAPT 8

// ---------------------------------------------------------------------------
// Global scratch (bf16 split pairs, packed 2 x bf16 per uint32)
// Bx: [b][s][r]   A-transposed: [a][o][r]
// ---------------------------------------------------------------------------
__device__ __align__(16) uint32_t g_bxh[BATCH * SEQ * RANK / 2];
__device__ __align__(16) uint32_t g_bxl[BATCH * SEQ * RANK / 2];
__device__ __align__(16) uint32_t g_ath[NADAPT * OUTF * RANK / 2];
__device__ __align__(16) uint32_t g_atl[NADAPT * OUTF * RANK / 2];

#define SW128(b) ((b) ^ (((b) >> 3) & 0x70))

__device__ __forceinline__ uint32_t smem_u32(const void* p) {
    uint32_t a;
    asm("{ .reg .u64 t; cvta.to.shared.u64 t, %1; cvt.u32.u64 %0, t; }"
        : "=r"(a) : "l"(p));
    return a;
}

__device__ __forceinline__ void ldsm4(uint32_t r[4], uint32_t addr) {
    asm volatile("ldmatrix.sync.aligned.m8n8.x4.shared.b16 {%0,%1,%2,%3}, [%4];"
        : "=r"(r[0]), "=r"(r[1]), "=r"(r[2]), "=r"(r[3]) : "r"(addr));
}

__device__ __forceinline__ void mma16816(float c[4], const uint32_t a[4],
                                         uint32_t b0, uint32_t b1) {
    asm volatile(
        "mma.sync.aligned.m16n8k16.row.col.f32.bf16.bf16.f32 "
        "{%0,%1,%2,%3}, {%4,%5,%6,%7}, {%8,%9}, {%0,%1,%2,%3};"
        : "+f"(c[0]), "+f"(c[1]), "+f"(c[2]), "+f"(c[3])
        : "r"(a[0]), "r"(a[1]), "r"(a[2]), "r"(a[3]), "r"(b0), "r"(b1));
}

// 3-term split-precision accumulate: c += Ah*Bh + Ah*Bl + Al*Bh
__device__ __forceinline__ void mma3(float c[4],
        const uint32_t ah[4], const uint32_t al[4],
        uint32_t bh0, uint32_t bh1, uint32_t bl0, uint32_t bl1) {
    mma16816(c, ah, bh0, bh1);
    mma16816(c, ah, bl0, bl1);
    mma16816(c, al, bh0, bh1);
}

#define CPASYNC16(sm, gp) \
    asm volatile("cp.async.cg.shared.global [%0], [%1], 16;" \
                 :: "r"(sm), "l"(gp) : "memory")
#define CPASYNC_COMMIT() asm volatile("cp.async.commit_group;" ::: "memory")
#define CPASYNC_WAIT0()  asm volatile("cp.async.wait_group 0;" ::: "memory")

// bf16 hi/lo split of a float pair -> two packed bf16x2 words (lo elem = a)
__device__ __forceinline__ void split2(float a, float b, uint32_t &h, uint32_t &l) {
    uint32_t hp;
    asm("cvt.rn.bf16x2.f32 %0, %1, %2;" : "=r"(hp) : "f"(b), "f"(a));
    float fa = __uint_as_float(hp << 16);
    float fb = __uint_as_float(hp & 0xFFFF0000u);
    float ra = a - fa, rb = b - fb;
    uint32_t lp;
    asm("cvt.rn.bf16x2.f32 %0, %1, %2;" : "=r"(lp) : "f"(rb), "f"(ra));
    h = hp; l = lp;
}

// ===========================================================================
// prep_A: A[a][r][o] fp32 -> g_ath/g_atl [a][o][r] bf16 (K-major)
// grid (32 o-tiles, 8 adapters), 256 thr
// ===========================================================================
__global__ __launch_bounds__(256) void lora_prep_a(const float* __restrict__ A) {
    __shared__ float As[64][132];
    const int a  = blockIdx.y;
    const int o0 = blockIdx.x * 128;
    const int tid = threadIdx.x;

    #pragma unroll
    for (int i = 0; i < 8; ++i) {
        int idx = tid + i * 256;
        int r = idx >> 5, og = idx & 31;
        *(float4*)&As[r][og * 4] =
            *(const float4*)(A + (size_t)a * RANK * OUTF + (size_t)r * OUTF + o0 + og * 4);
    }
    __syncthreads();

    const int o = tid >> 1, r0 = (tid & 1) * 32;
    __align__(16) uint32_t hb[16], lb[16];
    #pragma unroll
    for (int j = 0; j < 16; ++j)
        split2(As[r0 + 2 * j][o], As[r0 + 2 * j + 1][o], hb[j], lb[j]);

    size_t base = ((size_t)(a * OUTF + o0 + o) * RANK + r0) / 2;
    #pragma unroll
    for (int q = 0; q < 4; ++q) {
        *(uint4*)(g_ath + base + q * 4) = *(uint4*)(hb + q * 4);
        *(uint4*)(g_atl + base + q * 4) = *(uint4*)(lb + q * 4);
    }
}

// ===========================================================================
// Stage 1: Bx[b][s][r] = x[b][s][:] @ B[:][a][r]
// CTA 64M x 64N, K=4096 in 64-chunks, ping-pong smem, ONE barrier per chunk.
// 8 warps = 2M x 4N, warp tile 32x16. grid (64, 4) = 256 CTAs.
// dyn smem 64 KB (XH/XL/BH/BL, each 2 x 8 KB ping-pong).
// ===========================================================================
#define S1_XH 0
#define S1_XL 16384
#define S1_BH 32768
#define S1_BL 49152
#define S1_SMEM 65536
#define S1_BUF 8192

__global__ __launch_bounds__(256, 2) void lora_s1(
    const float* __restrict__ x, const int* __restrict__ ids,
    const float* __restrict__ Bw)
{
    extern __shared__ __align__(128) uint8_t sm1[];
    const int tid = threadIdx.x, lane = tid & 31, wid = tid >> 5;
    const int wm = wid & 1, wn = wid >> 1;           // 2M x 4N warps
    const int b = blockIdx.y;
    const int a = ids[b];
    const int m0 = blockIdx.x * 64;

    const uint32_t smb = smem_u32(sm1);
    const int lr = lane & 15;
    const uint32_t lcol = (uint32_t)(lane >> 4) * 16;

    uint32_t aterm[2], axor[2];
    #pragma unroll
    for (int t = 0; t < 2; ++t) {
        int ar = wm * 32 + t * 16 + lr;
        aterm[t] = (uint32_t)ar * 128; axor[t] = (uint32_t)(ar & 7) << 4;
    }
    const int br = wn * 16 + lr;
    const uint32_t bterm = (uint32_t)br * 128, bxor = (uint32_t)(br & 7) << 4;

    float acc[2][2][4];
    #pragma unroll
    for (int i = 0; i < 2; ++i)
        #pragma unroll
        for (int j = 0; j < 2; ++j)
            #pragma unroll
            for (int k = 0; k < 4; ++k) acc[i][j][k] = 0.f;

    // per-thread load/convert coordinates
    const int xm[4] = { tid >> 4, (tid + 256) >> 4, (tid + 512) >> 4, (tid + 768) >> 4 };
    const int xkg = tid & 15;
    const int bih = tid & 31;                // h-pair index (lane-fast: STS conflict-free)
    const int brg[2] = { tid >> 5, (tid + 256) >> 5 };

    float4 xv[4], bv0[2], bv1[2];

    // ---- prefetch chunk 0 ----
    #pragma unroll
    for (int i = 0; i < 4; ++i)
        xv[i] = *(const float4*)(x + (size_t)(b * SEQ + m0 + xm[i]) * HID + xkg * 4);
    #pragma unroll
    for (int i = 0; i < 2; ++i) {
        const float* p = Bw + (size_t)(2 * bih) * (NADAPT * RANK) + a * RANK + brg[i] * 4;
        bv0[i] = *(const float4*)p;
        bv1[i] = *(const float4*)(p + NADAPT * RANK);
    }

    // ---- convert chunk 0 into buf 0 ----
    #pragma unroll
    for (int i = 0; i < 4; ++i) {
        uint32_t h0, l0, h1, l1;
        split2(xv[i].x, xv[i].y, h0, l0);
        split2(xv[i].z, xv[i].w, h1, l1);
        uint32_t off = (uint32_t)xm[i] * 128 + xkg * 8;
        uint32_t s0 = SW128(off), s1 = SW128(off + 4);
        *(uint32_t*)(sm1 + S1_XH + s0) = h0;
        *(uint32_t*)(sm1 + S1_XL + s0) = l0;
        *(uint32_t*)(sm1 + S1_XH + s1) = h1;
        *(uint32_t*)(sm1 + S1_XL + s1) = l1;
    }
    #pragma unroll
    for (int i = 0; i < 2; ++i) {
        const float* f0 = &bv0[i].x;
        const float* f1 = &bv1[i].x;
        #pragma unroll
        for (int j = 0; j < 4; ++j) {
            uint32_t h, l;
            split2(f0[j], f1[j], h, l);     // packs (k=2ih, k=2ih+1) for rank r
            uint32_t so = SW128((uint32_t)(brg[i] * 4 + j) * 128 + bih * 4);
            *(uint32_t*)(sm1 + S1_BH + so) = h;
            *(uint32_t*)(sm1 + S1_BL + so) = l;
        }
    }
    __syncthreads();

    for (int it = 0; it < HID / 64; ++it) {
        const uint32_t pb = (uint32_t)(it & 1) * S1_BUF;

        // ---- issue prefetch for chunk it+1 (latency hides under MMA) ----
        if (it + 1 < HID / 64) {
            int kc = (it + 1) * 64;
            #pragma unroll
            for (int i = 0; i < 4; ++i)
                xv[i] = *(const float4*)(x + (size_t)(b * SEQ + m0 + xm[i]) * HID + kc + xkg * 4);
            #pragma unroll
            for (int i = 0; i < 2; ++i) {
                const float* p = Bw + (size_t)(kc + 2 * bih) * (NADAPT * RANK) + a * RANK + brg[i] * 4;
                bv0[i] = *(const float4*)p;
                bv1[i] = *(const float4*)(p + NADAPT * RANK);
            }
        }

        // ---- MMA over buf p ----
        #pragma unroll
        for (int ks = 0; ks < 4; ++ks) {
            uint32_t cb = lcol + (uint32_t)ks * 32;
            uint32_t ah0[4], ah1[4], al0[4], al1[4];
            ldsm4(ah0, smb + S1_XH + pb + aterm[0] + (cb ^ axor[0]));
            ldsm4(ah1, smb + S1_XH + pb + aterm[1] + (cb ^ axor[1]));
            ldsm4(al0, smb + S1_XL + pb + aterm[0] + (cb ^ axor[0]));
            ldsm4(al1, smb + S1_XL + pb + aterm[1] + (cb ^ axor[1]));
            uint32_t bh[4], bl[4];
            ldsm4(bh, smb + S1_BH + pb + bterm + (cb ^ bxor));
            ldsm4(bl, smb + S1_BL + pb + bterm + (cb ^ bxor));

            mma3(acc[0][0], ah0, al0, bh[0], bh[2], bl[0], bl[2]);
            mma3(acc[0][1], ah0, al0, bh[1], bh[3], bl[1], bl[3]);
            mma3(acc[1][0], ah1, al1, bh[0], bh[2], bl[0], bl[2]);
            mma3(acc[1][1], ah1, al1, bh[1], bh[3], bl[1], bl[3]);
        }

        // ---- convert chunk it+1 into buf p^1 (overlaps other warps' MMA) ----
        if (it + 1 < HID / 64) {
            const uint32_t qb = pb ^ S1_BUF;
            #pragma unroll
            for (int i = 0; i < 4; ++i) {
                uint32_t h0, l0, h1, l1;
                split2(xv[i].x, xv[i].y, h0, l0);
                split2(xv[i].z, xv[i].w, h1, l1);
                uint32_t off = (uint32_t)xm[i] * 128 + xkg * 8;
                uint32_t s0 = SW128(off), s1 = SW128(off + 4);
                *(uint32_t*)(sm1 + S1_XH + qb + s0) = h0;
                *(uint32_t*)(sm1 + S1_XL + qb + s0) = l0;
                *(uint32_t*)(sm1 + S1_XH + qb + s1) = h1;
                *(uint32_t*)(sm1 + S1_XL + qb + s1) = l1;
            }
            #pragma unroll
            for (int i = 0; i < 2; ++i) {
                const float* f0 = &bv0[i].x;
                const float* f1 = &bv1[i].x;
                #pragma unroll
                for (int j = 0; j < 4; ++j) {
                    uint32_t h, l;
                    split2(f0[j], f1[j], h, l);
                    uint32_t so = SW128((uint32_t)(brg[i] * 4 + j) * 128 + bih * 4);
                    *(uint32_t*)(sm1 + S1_BH + qb + so) = h;
                    *(uint32_t*)(sm1 + S1_BL + qb + so) = l;
                }
            }
        }
        __syncthreads();
    }

    // ---- epilogue: c-pairs are adjacent r values -> bf16 hi/lo packed ----
    #pragma unroll
    for (int mt = 0; mt < 2; ++mt)
        #pragma unroll
        for (int nt = 0; nt < 2; ++nt)
            #pragma unroll
            for (int rh = 0; rh < 2; ++rh) {
                int s = m0 + wm * 32 + mt * 16 + rh * 8 + (lane >> 2);
                int r = wn * 16 + nt * 8 + 2 * (lane & 3);
                uint32_t h, l;
                split2(acc[mt][nt][2 * rh], acc[mt][nt][2 * rh + 1], h, l);
                size_t idx = (size_t)(b * SEQ + s) * (RANK / 2) + (r >> 1);
                g_bxh[idx] = h;
                g_bxl[idx] = l;
            }
}

// ===========================================================================
// Stage 2: out[b][s][o] = Bx[b][s][:] @ At[a][o][:] / 64
// CTA 128M x 64N, K=64 one-shot, cp.async smem fill. grid (64, 32, 4).
// ===========================================================================
__global__ __launch_bounds__(256, 2) void lora_s2(
    const int* __restrict__ ids, float* __restrict__ out)
{
    __shared__ __align__(128) uint8_t sXh[128 * 128];   // Bx [m][k]
    __shared__ __align__(128) uint8_t sXl[128 * 128];
    __shared__ __align__(128) uint8_t sAh[64 * 128];    // At [o][k]
    __shared__ __align__(128) uint8_t sAl[64 * 128];

    const int tid = threadIdx.x, lane = tid & 31, wid = tid >> 5;
    const int wm = wid & 3, wn = wid >> 2;
    const int o0 = blockIdx.x * 64, m0 = blockIdx.y * 128, b = blockIdx.z;
    const int a = ids[b];

    const uint32_t xh_b = smem_u32(sXh), xl_b = smem_u32(sXl);
    const uint32_t nh_b = smem_u32(sAh), nl_b = smem_u32(sAl);

    // ---- cp.async smem fill (no register staging) ----
    #pragma unroll
    for (int i = 0; i < 4; ++i) {
        int idx = tid + i * 256;             // 1024 uint4 slots
        int row = idx >> 3, rg = idx & 7;
        uint32_t so = SW128((uint32_t)row * 128 + rg * 16);
        size_t bx = (size_t)(b * SEQ + m0 + row) * 8 + rg;
        CPASYNC16(xh_b + so, (const uint4*)g_bxh + bx);
        CPASYNC16(xl_b + so, (const uint4*)g_bxl + bx);
    }
    #pragma unroll
    for (int i = 0; i < 2; ++i) {
        int idx = tid + i * 256;             // 512 uint4 slots
        int row = idx >> 3, rg = idx & 7;
        uint32_t so = SW128((uint32_t)row * 128 + rg * 16);
        size_t at = (size_t)(a * OUTF + o0 + row) * 8 + rg;
        CPASYNC16(nh_b + so, (const uint4*)g_ath + at);
        CPASYNC16(nl_b + so, (const uint4*)g_atl + at);
    }
    CPASYNC_COMMIT();
    CPASYNC_WAIT0();
    __syncthreads();

    const int lr = lane & 15;
    const uint32_t lcol = (uint32_t)(lane >> 4) * 16;

    uint32_t aterm[2], axor[2], bterm[2], bxor[2];
    #pragma unroll
    for (int t = 0; t < 2; ++t) {
        int ar = wm * 32 + t * 16 + lr;
        aterm[t] = (uint32_t)ar * 128; axor[t] = (uint32_t)(ar & 7) << 4;
        int brr = wn * 32 + t * 16 + lr;
        bterm[t] = (uint32_t)brr * 128; bxor[t] = (uint32_t)(brr & 7) << 4;
    }

    float acc[2][4][4];
    #pragma unroll
    for (int i = 0; i < 2; ++i)
        #pragma unroll
        for (int j = 0; j < 4; ++j)
            #pragma unroll
            for (int k = 0; k < 4; ++k) acc[i][j][k] = 0.f;

    #pragma unroll
    for (int ks = 0; ks < 4; ++ks) {
        uint32_t cb = lcol + (uint32_t)ks * 32;
        uint32_t ah0[4], ah1[4], al0[4], al1[4];
        ldsm4(ah0, xh_b + aterm[0] + (cb ^ axor[0]));
        ldsm4(ah1, xh_b + aterm[1] + (cb ^ axor[1]));
        ldsm4(al0, xl_b + aterm[0] + (cb ^ axor[0]));
        ldsm4(al1, xl_b + aterm[1] + (cb ^ axor[1]));
        uint32_t bh0[4], bh1[4], bl0[4], bl1[4];
        ldsm4(bh0, nh_b + bterm[0] + (cb ^ bxor[0]));
        ldsm4(bh1, nh_b + bterm[1] + (cb ^ bxor[1]));
        ldsm4(bl0, nl_b + bterm[0] + (cb ^ bxor[0]));
        ldsm4(bl1, nl_b + bterm[1] + (cb ^ bxor[1]));

        mma3(acc[0][0], ah0, al0, bh0[0], bh0[2], bl0[0], bl0[2]);
        mma3(acc[0][1], ah0, al0, bh0[1], bh0[3], bl0[1], bl0[3]);
        mma3(acc[0][2], ah0, al0, bh1[0], bh1[2], bl1[0], bl1[2]);
        mma3(acc[0][3], ah0, al0, bh1[1], bh1[3], bl1[1], bl1[3]);
        mma3(acc[1][0], ah1, al1, bh0[0], bh0[2], bl0[0], bl0[2]);
        mma3(acc[1][1], ah1, al1, bh0[1], bh0[3], bl0[1], bl0[3]);
        mma3(acc[1][2], ah1, al1, bh1[0], bh1[2], bl1[0], bl1[2]);
        mma3(acc[1][3], ah1, al1, bh1[1], bh1[3], bl1[1], bl1[3]);
    }

    // ---- epilogue: scaled direct stores ----
    const float sc = 1.0f / (float)RANK;
    #pragma unroll
    for (int mt = 0; mt < 2; ++mt)
        #pragma unroll
        for (int nt = 0; nt < 4; ++nt) {
            int row = m0 + wm * 32 + mt * 16 + (lane >> 2);
            int col = o0 + wn * 32 + nt * 8 + 2 * (lane & 3);
            float2 v0 = { acc[mt][nt][0] * sc, acc[mt][nt][1] * sc };
            float2 v1 = { acc[mt][nt][2] * sc, acc[mt][nt][3] * sc };
            *(float2*)(out + (size_t)(b * SEQ + row)     * OUTF + col) = v0;
            *(float2*)(out + (size_t)(b * SEQ + row + 8) * OUTF + col) = v1;
        }
}

// ===========================================================================
extern "C" void kernel_launch(void* const* d_in, const int* in_sizes, int n_in,
                              void* d_out, int out_size)
{
    const float* x   = (const float*)d_in[0];
    const int*   ids = (const int*)  d_in[1];
    const float* A   = (const float*)d_in[2];
    const float* Bw  = (const float*)d_in[3];
    float* out = (float*)d_out;

    cudaFuncSetAttribute(lora_s1, cudaFuncAttributeMaxDynamicSharedMemorySize, S1_SMEM);

    lora_prep_a<<<dim3(OUTF / 128, NADAPT), 256>>>(A);
    lora_s1<<<dim3(SEQ / 64, BATCH), 256, S1_SMEM>>>(x, ids, Bw);
    lora_s2<<<dim3(OUTF / 64, SEQ / 128, BATCH), 256>>>(ids, out);
}

// round 6
// speedup vs baseline: 1.5877x; 1.5877x over previous
#include <cuda_runtime.h>
#include <cuda_bf16.h>
#include <cstdint>

#define BATCH  4
#define SEQ    4096
#define HID    4096
#define OUTF   4096
#define RANK   64
#define NADAPT 8

// ---------------------------------------------------------------------------
// Global scratch (bf16 split pairs, packed 2 x bf16 per uint32)
// Bx: [b][s][r]   A-transposed: [a][o][r]
// ---------------------------------------------------------------------------
__device__ __align__(16) uint32_t g_bxh[BATCH * SEQ * RANK / 2];
__device__ __align__(16) uint32_t g_bxl[BATCH * SEQ * RANK / 2];
__device__ __align__(16) uint32_t g_ath[NADAPT * OUTF * RANK / 2];
__device__ __align__(16) uint32_t g_atl[NADAPT * OUTF * RANK / 2];

#define SW128(b) ((b) ^ (((b) >> 3) & 0x70))

__device__ __forceinline__ uint32_t smem_u32(const void* p) {
    uint32_t a;
    asm("{ .reg .u64 t; cvta.to.shared.u64 t, %1; cvt.u32.u64 %0, t; }"
        : "=r"(a) : "l"(p));
    return a;
}

__device__ __forceinline__ void ldsm4(uint32_t r[4], uint32_t addr) {
    asm volatile("ldmatrix.sync.aligned.m8n8.x4.shared.b16 {%0,%1,%2,%3}, [%4];"
        : "=r"(r[0]), "=r"(r[1]), "=r"(r[2]), "=r"(r[3]) : "r"(addr));
}

__device__ __forceinline__ void mma16816(float c[4], const uint32_t a[4],
                                         uint32_t b0, uint32_t b1) {
    asm volatile(
        "mma.sync.aligned.m16n8k16.row.col.f32.bf16.bf16.f32 "
        "{%0,%1,%2,%3}, {%4,%5,%6,%7}, {%8,%9}, {%0,%1,%2,%3};"
        : "+f"(c[0]), "+f"(c[1]), "+f"(c[2]), "+f"(c[3])
        : "r"(a[0]), "r"(a[1]), "r"(a[2]), "r"(a[3]), "r"(b0), "r"(b1));
}

// 3-term split-precision accumulate: c += Ah*Bh + Ah*Bl + Al*Bh
__device__ __forceinline__ void mma3(float c[4],
        const uint32_t ah[4], const uint32_t al[4],
        uint32_t bh0, uint32_t bh1, uint32_t bl0, uint32_t bl1) {
    mma16816(c, ah, bh0, bh1);
    mma16816(c, ah, bl0, bl1);
    mma16816(c, al, bh0, bh1);
}

#define CPASYNC16(sm, gp) \
    asm volatile("cp.async.cg.shared.global [%0], [%1], 16;" \
                 :: "r"(sm), "l"(gp) : "memory")
#define CPASYNC_COMMIT() asm volatile("cp.async.commit_group;" ::: "memory")
#define CPASYNC_WAIT0()  asm volatile("cp.async.wait_group 0;" ::: "memory")

// bf16 hi/lo split of a float pair -> two packed bf16x2 words (lo elem = a)
__device__ __forceinline__ void split2(float a, float b, uint32_t &h, uint32_t &l) {
    uint32_t hp;
    asm("cvt.rn.bf16x2.f32 %0, %1, %2;" : "=r"(hp) : "f"(b), "f"(a));
    float fa = __uint_as_float(hp << 16);
    float fb = __uint_as_float(hp & 0xFFFF0000u);
    float ra = a - fa, rb = b - fb;
    uint32_t lp;
    asm("cvt.rn.bf16x2.f32 %0, %1, %2;" : "=r"(lp) : "f"(rb), "f"(ra));
    h = hp; l = lp;
}

// ===========================================================================
// prep_A: A[a][r][o] fp32 -> g_ath/g_atl [a][o][r] bf16 (K-major)
// grid (32 o-tiles, 8 adapters), 256 thr
// ===========================================================================
__global__ __launch_bounds__(256) void lora_prep_a(const float* __restrict__ A) {
    __shared__ float As[64][132];
    const int a  = blockIdx.y;
    const int o0 = blockIdx.x * 128;
    const int tid = threadIdx.x;

    #pragma unroll
    for (int i = 0; i < 8; ++i) {
        int idx = tid + i * 256;
        int r = idx >> 5, og = idx & 31;
        *(float4*)&As[r][og * 4] =
            *(const float4*)(A + (size_t)a * RANK * OUTF + (size_t)r * OUTF + o0 + og * 4);
    }
    __syncthreads();

    const int o = tid >> 1, r0 = (tid & 1) * 32;
    __align__(16) uint32_t hb[16], lb[16];
    #pragma unroll
    for (int j = 0; j < 16; ++j)
        split2(As[r0 + 2 * j][o], As[r0 + 2 * j + 1][o], hb[j], lb[j]);

    size_t base = ((size_t)(a * OUTF + o0 + o) * RANK + r0) / 2;
    #pragma unroll
    for (int q = 0; q < 4; ++q) {
        *(uint4*)(g_ath + base + q * 4) = *(uint4*)(hb + q * 4);
        *(uint4*)(g_atl + base + q * 4) = *(uint4*)(lb + q * 4);
    }
}

// ===========================================================================
// Stage 1: Bx[b][s][r] = x[b][s][:] @ B[:][a][r]
// CTA 128M x 64N (R4 geometry), K=4096 in 64-chunks, PING-PONG smem,
// ONE barrier per chunk. 8 warps = 4M x 2N, warp tile 32x32.
// grid (32, 4) = 128 CTAs. dyn smem 96 KB (2 x 48 KB buffers).
// ===========================================================================
#define S1_XH 0
#define S1_XL 16384
#define S1_BH 32768
#define S1_BL 40960
#define S1_BUF 49152
#define S1_SMEM (2 * S1_BUF)

__global__ __launch_bounds__(256, 1) void lora_s1(
    const float* __restrict__ x, const int* __restrict__ ids,
    const float* __restrict__ Bw)
{
    extern __shared__ __align__(128) uint8_t sm1[];
    const int tid = threadIdx.x, lane = tid & 31, wid = tid >> 5;
    const int wm = wid & 3, wn = wid >> 2;           // 4M x 2N warps
    const int b = blockIdx.y;
    const int a = ids[b];
    const int m0 = blockIdx.x * 128;

    const uint32_t smb = smem_u32(sm1);
    const int lr = lane & 15;
    const uint32_t lcol = (uint32_t)(lane >> 4) * 16;

    uint32_t aterm[2], axor[2], bterm[2], bxor[2];
    #pragma unroll
    for (int t = 0; t < 2; ++t) {
        int ar = wm * 32 + t * 16 + lr;
        aterm[t] = (uint32_t)ar * 128; axor[t] = (uint32_t)(ar & 7) << 4;
        int br = wn * 32 + t * 16 + lr;
        bterm[t] = (uint32_t)br * 128; bxor[t] = (uint32_t)(br & 7) << 4;
    }

    float acc[2][4][4];
    #pragma unroll
    for (int i = 0; i < 2; ++i)
        #pragma unroll
        for (int j = 0; j < 4; ++j)
            #pragma unroll
            for (int k = 0; k < 4; ++k) acc[i][j][k] = 0.f;

    // per-thread load/convert coordinates
    const int xkg = tid & 15;                 // k-group within 64 (4 k each)
    const int bih = tid & 31;                 // h-pair (lane-fast: STS conflict-free)
    const int brg0 = tid >> 5;                // rank groups 0..7 and 8..15

    float4 xv[8], bv0[2], bv1[2];

    // ---- prefetch chunk 0 ----
    #pragma unroll
    for (int i = 0; i < 8; ++i) {
        int m = (tid + i * 256) >> 4;
        xv[i] = *(const float4*)(x + (size_t)(b * SEQ + m0 + m) * HID + xkg * 4);
    }
    #pragma unroll
    for (int i = 0; i < 2; ++i) {
        const float* p = Bw + (size_t)(2 * bih) * (NADAPT * RANK) + a * RANK
                       + (brg0 + i * 8) * 4;
        bv0[i] = *(const float4*)p;
        bv1[i] = *(const float4*)(p + NADAPT * RANK);
    }

    // ---- convert chunk 0 into buf 0 ----
    #pragma unroll
    for (int i = 0; i < 8; ++i) {
        int m = (tid + i * 256) >> 4;
        uint32_t h0, l0, h1, l1;
        split2(xv[i].x, xv[i].y, h0, l0);
        split2(xv[i].z, xv[i].w, h1, l1);
        uint32_t s0 = SW128((uint32_t)m * 128 + xkg * 8);   // +4 shares swizzle
        *(uint2*)(sm1 + S1_XH + s0) = make_uint2(h0, h1);
        *(uint2*)(sm1 + S1_XL + s0) = make_uint2(l0, l1);
    }
    #pragma unroll
    for (int i = 0; i < 2; ++i) {
        const float* f0 = &bv0[i].x;
        const float* f1 = &bv1[i].x;
        #pragma unroll
        for (int j = 0; j < 4; ++j) {
            uint32_t h, l;
            split2(f0[j], f1[j], h, l);     // packs (k=2ih, 2ih+1) for rank r
            uint32_t so = SW128((uint32_t)((brg0 + i * 8) * 4 + j) * 128 + bih * 4);
            *(uint32_t*)(sm1 + S1_BH + so) = h;
            *(uint32_t*)(sm1 + S1_BL + so) = l;
        }
    }
    __syncthreads();

    for (int it = 0; it < HID / 64; ++it) {
        const uint32_t pb = (uint32_t)(it & 1) * S1_BUF;

        // ---- prefetch chunk it+1 (LDG latency hides under MMA) ----
        if (it + 1 < HID / 64) {
            int kc = (it + 1) * 64;
            #pragma unroll
            for (int i = 0; i < 8; ++i) {
                int m = (tid + i * 256) >> 4;
                xv[i] = *(const float4*)(x + (size_t)(b * SEQ + m0 + m) * HID + kc + xkg * 4);
            }
            #pragma unroll
            for (int i = 0; i < 2; ++i) {
                const float* p = Bw + (size_t)(kc + 2 * bih) * (NADAPT * RANK) + a * RANK
                               + (brg0 + i * 8) * 4;
                bv0[i] = *(const float4*)p;
                bv1[i] = *(const float4*)(p + NADAPT * RANK);
            }
        }

        // ---- MMA over buf pb ----
        #pragma unroll
        for (int ks = 0; ks < 4; ++ks) {
            uint32_t cb = lcol + (uint32_t)ks * 32;
            uint32_t ah0[4], ah1[4], al0[4], al1[4];
            ldsm4(ah0, smb + S1_XH + pb + aterm[0] + (cb ^ axor[0]));
            ldsm4(ah1, smb + S1_XH + pb + aterm[1] + (cb ^ axor[1]));
            ldsm4(al0, smb + S1_XL + pb + aterm[0] + (cb ^ axor[0]));
            ldsm4(al1, smb + S1_XL + pb + aterm[1] + (cb ^ axor[1]));
            uint32_t bh0[4], bh1[4], bl0[4], bl1[4];
            ldsm4(bh0, smb + S1_BH + pb + bterm[0] + (cb ^ bxor[0]));
            ldsm4(bh1, smb + S1_BH + pb + bterm[1] + (cb ^ bxor[1]));
            ldsm4(bl0, smb + S1_BL + pb + bterm[0] + (cb ^ bxor[0]));
            ldsm4(bl1, smb + S1_BL + pb + bterm[1] + (cb ^ bxor[1]));

            mma3(acc[0][0], ah0, al0, bh0[0], bh0[2], bl0[0], bl0[2]);
            mma3(acc[0][1], ah0, al0, bh0[1], bh0[3], bl0[1], bl0[3]);
            mma3(acc[0][2], ah0, al0, bh1[0], bh1[2], bl1[0], bl1[2]);
            mma3(acc[0][3], ah0, al0, bh1[1], bh1[3], bl1[1], bl1[3]);
            mma3(acc[1][0], ah1, al1, bh0[0], bh0[2], bl0[0], bl0[2]);
            mma3(acc[1][1], ah1, al1, bh0[1], bh0[3], bl0[1], bl0[3]);
            mma3(acc[1][2], ah1, al1, bh1[0], bh1[2], bl1[0], bl1[2]);
            mma3(acc[1][3], ah1, al1, bh1[1], bh1[3], bl1[1], bl1[3]);
        }

        // ---- convert chunk it+1 into the other buffer ----
        if (it + 1 < HID / 64) {
            const uint32_t qb = pb ^ S1_BUF;
            #pragma unroll
            for (int i = 0; i < 8; ++i) {
                int m = (tid + i * 256) >> 4;
                uint32_t h0, l0, h1, l1;
                split2(xv[i].x, xv[i].y, h0, l0);
                split2(xv[i].z, xv[i].w, h1, l1);
                uint32_t s0 = SW128((uint32_t)m * 128 + xkg * 8);
                *(uint2*)(sm1 + S1_XH + qb + s0) = make_uint2(h0, h1);
                *(uint2*)(sm1 + S1_XL + qb + s0) = make_uint2(l0, l1);
            }
            #pragma unroll
            for (int i = 0; i < 2; ++i) {
                const float* f0 = &bv0[i].x;
                const float* f1 = &bv1[i].x;
                #pragma unroll
                for (int j = 0; j < 4; ++j) {
                    uint32_t h, l;
                    split2(f0[j], f1[j], h, l);
                    uint32_t so = SW128((uint32_t)((brg0 + i * 8) * 4 + j) * 128 + bih * 4);
                    *(uint32_t*)(sm1 + S1_BH + qb + so) = h;
                    *(uint32_t*)(sm1 + S1_BL + qb + so) = l;
                }
            }
        }
        __syncthreads();
    }

    // ---- epilogue: c-pairs are adjacent r values -> bf16 hi/lo packed ----
    #pragma unroll
    for (int mt = 0; mt < 2; ++mt)
        #pragma unroll
        for (int nt = 0; nt < 4; ++nt)
            #pragma unroll
            for (int rh = 0; rh < 2; ++rh) {
                int s = m0 + wm * 32 + mt * 16 + rh * 8 + (lane >> 2);
                int r = wn * 32 + nt * 8 + 2 * (lane & 3);
                uint32_t h, l;
                split2(acc[mt][nt][2 * rh], acc[mt][nt][2 * rh + 1], h, l);
                size_t idx = (size_t)(b * SEQ + s) * (RANK / 2) + (r >> 1);
                g_bxh[idx] = h;
                g_bxl[idx] = l;
            }
}

// ===========================================================================
// Stage 2: out[b][s][o] = Bx[b][s][:] @ At[a][o][:] / 64
// CTA 128M x 128N, K=64 one-shot, 512 thr = 16 warps (4M x 4N, 32x32 each).
// cp.async fill, 64 KB dyn smem. grid (32, 32, 4) = 4096 CTAs.
// ===========================================================================
#define S2_XH 0
#define S2_XL 16384
#define S2_AH 32768
#define S2_AL 49152
#define S2_SMEM 65536

__global__ __launch_bounds__(512, 1) void lora_s2(
    const int* __restrict__ ids, float* __restrict__ out)
{
    extern __shared__ __align__(128) uint8_t sm2[];
    const int tid = threadIdx.x, lane = tid & 31, wid = tid >> 5;
    const int wm = wid & 3, wn = wid >> 2;           // 4M x 4N warps
    const int o0 = blockIdx.x * 128, m0 = blockIdx.y * 128, b = blockIdx.z;
    const int a = ids[b];

    const uint32_t smb = smem_u32(sm2);

    // ---- cp.async smem fill ----
    #pragma unroll
    for (int i = 0; i < 2; ++i) {
        int idx = tid + i * 512;             // 1024 uint4 slots per array
        int row = idx >> 3, rg = idx & 7;
        uint32_t so = SW128((uint32_t)row * 128 + rg * 16);
        size_t bx = (size_t)(b * SEQ + m0 + row) * 8 + rg;
        size_t at = (size_t)(a * OUTF + o0 + row) * 8 + rg;
        CPASYNC16(smb + S2_XH + so, (const uint4*)g_bxh + bx);
        CPASYNC16(smb + S2_XL + so, (const uint4*)g_bxl + bx);
        CPASYNC16(smb + S2_AH + so, (const uint4*)g_ath + at);
        CPASYNC16(smb + S2_AL + so, (const uint4*)g_atl + at);
    }
    CPASYNC_COMMIT();
    CPASYNC_WAIT0();
    __syncthreads();

    const int lr = lane & 15;
    const uint32_t lcol = (uint32_t)(lane >> 4) * 16;

    uint32_t aterm[2], axor[2], bterm[2], bxor[2];
    #pragma unroll
    for (int t = 0; t < 2; ++t) {
        int ar = wm * 32 + t * 16 + lr;
        aterm[t] = (uint32_t)ar * 128; axor[t] = (uint32_t)(ar & 7) << 4;
        int br = wn * 32 + t * 16 + lr;
        bterm[t] = (uint32_t)br * 128; bxor[t] = (uint32_t)(br & 7) << 4;
    }

    float acc[2][4][4];
    #pragma unroll
    for (int i = 0; i < 2; ++i)
        #pragma unroll
        for (int j = 0; j < 4; ++j)
            #pragma unroll
            for (int k = 0; k < 4; ++k) acc[i][j][k] = 0.f;

    #pragma unroll
    for (int ks = 0; ks < 4; ++ks) {
        uint32_t cb = lcol + (uint32_t)ks * 32;
        uint32_t ah0[4], ah1[4], al0[4], al1[4];
        ldsm4(ah0, smb + S2_XH + aterm[0] + (cb ^ axor[0]));
        ldsm4(ah1, smb + S2_XH + aterm[1] + (cb ^ axor[1]));
        ldsm4(al0, smb + S2_XL + aterm[0] + (cb ^ axor[0]));
        ldsm4(al1, smb + S2_XL + aterm[1] + (cb ^ axor[1]));
        uint32_t bh0[4], bh1[4], bl0[4], bl1[4];
        ldsm4(bh0, smb + S2_AH + bterm[0] + (cb ^ bxor[0]));
        ldsm4(bh1, smb + S2_AH + bterm[1] + (cb ^ bxor[1]));
        ldsm4(bl0, smb + S2_AL + bterm[0] + (cb ^ bxor[0]));
        ldsm4(bl1, smb + S2_AL + bterm[1] + (cb ^ bxor[1]));

        mma3(acc[0][0], ah0, al0, bh0[0], bh0[2], bl0[0], bl0[2]);
        mma3(acc[0][1], ah0, al0, bh0[1], bh0[3], bl0[1], bl0[3]);
        mma3(acc[0][2], ah0, al0, bh1[0], bh1[2], bl1[0], bl1[2]);
        mma3(acc[0][3], ah0, al0, bh1[1], bh1[3], bl1[1], bl1[3]);
        mma3(acc[1][0], ah1, al1, bh0[0], bh0[2], bl0[0], bl0[2]);
        mma3(acc[1][1], ah1, al1, bh0[1], bh0[3], bl0[1], bl0[3]);
        mma3(acc[1][2], ah1, al1, bh1[0], bh1[2], bl1[0], bl1[2]);
        mma3(acc[1][3], ah1, al1, bh1[1], bh1[3], bl1[1], bl1[3]);
    }

    // ---- epilogue: scaled direct stores ----
    const float sc = 1.0f / (float)RANK;
    #pragma unroll
    for (int mt = 0; mt < 2; ++mt)
        #pragma unroll
        for (int nt = 0; nt < 4; ++nt) {
            int row = m0 + wm * 32 + mt * 16 + (lane >> 2);
            int col = o0 + wn * 32 + nt * 8 + 2 * (lane & 3);
            float2 v0 = { acc[mt][nt][0] * sc, acc[mt][nt][1] * sc };
            float2 v1 = { acc[mt][nt][2] * sc, acc[mt][nt][3] * sc };
            *(float2*)(out + (size_t)(b * SEQ + row)     * OUTF + col) = v0;
            *(float2*)(out + (size_t)(b * SEQ + row + 8) * OUTF + col) = v1;
        }
}

// ===========================================================================
extern "C" void kernel_launch(void* const* d_in, const int* in_sizes, int n_in,
                              void* d_out, int out_size)
{
    const float* x   = (const float*)d_in[0];
    const int*   ids = (const int*)  d_in[1];
    const float* A   = (const float*)d_in[2];
    const float* Bw  = (const float*)d_in[3];
    float* out = (float*)d_out;

    cudaFuncSetAttribute(lora_s1, cudaFuncAttributeMaxDynamicSharedMemorySize, S1_SMEM);
    cudaFuncSetAttribute(lora_s2, cudaFuncAttributeMaxDynamicSharedMemorySize, S2_SMEM);

    lora_prep_a<<<dim3(OUTF / 128, NADAPT), 256>>>(A);
    lora_s1<<<dim3(SEQ / 128, BATCH), 256, S1_SMEM>>>(x, ids, Bw);
    lora_s2<<<dim3(OUTF / 128, SEQ / 128, BATCH), 512, S2_SMEM>>>(ids, out);
}